// round 11
// baseline (speedup 1.0000x reference)
#include <cuda_runtime.h>
#include <math.h>

#define BB 4
#define NN 2048
#define KNN 48
#define NRBF 16
#define NPE 16
#define EDGE_C 128
#define PE_IN 66
#define MAXREL 32
#define ROWS_PER_CTA 4
#define NBIN 2048
#define CAND_CAP 1024
#define EDGES_PER_WARP 8

// scratch (no cudaMalloc allowed)
__device__ float4 g_X4[BB * NN];              // xyz = masked coords, w = mask
__device__ float  g_PW[PE_IN * EDGE_C];       // (pe_w[d]+pe_b) @ edge_w[0:16]
__device__ float4 g_E4[BB * NN * KNN];        // per-edge (D, dc, tb, -)

// f32x2 packed helpers
__device__ __forceinline__ unsigned long long pk2(float a, float b) {
    unsigned long long r;
    asm("mov.b64 %0, {%1, %2};" : "=l"(r) : "f"(a), "f"(b));
    return r;
}
__device__ __forceinline__ void unpk2(unsigned long long v, float& a, float& b) {
    asm("mov.b64 {%0, %1}, %2;" : "=f"(a), "=f"(b) : "l"(v));
}
__device__ __forceinline__ unsigned long long fma2(unsigned long long a,
                                                   unsigned long long b,
                                                   unsigned long long c) {
    unsigned long long d;
    asm("fma.rn.f32x2 %0, %1, %2, %3;" : "=l"(d) : "l"(a), "l"(b), "l"(c));
    return d;
}

// ---------------------------------------------------------------------------
// Kernel 1 (fused setup): blocks 0..31 gather coords; blocks 32..64 build PW.
// ---------------------------------------------------------------------------
__global__ void setup_kernel(const float* __restrict__ coords,
                             const float* __restrict__ mask,
                             const int*   __restrict__ t2c,
                             const float* __restrict__ pe_w,
                             const float* __restrict__ pe_b,
                             const float* __restrict__ edge_w) {
    if (blockIdx.x < 32) {
        int t = blockIdx.x * 256 + threadIdx.x;   // b*N + n
        int b = t / NN;
        int a = t2c[t];
        float m = mask[t];
        const float* src = coords + ((size_t)b * NN + a) * 3;
        g_X4[t] = make_float4(src[0] * m, src[1] * m, src[2] * m, m);
    } else {
        int d = (blockIdx.x - 32) * 2 + (threadIdx.x >> 7);   // 0..65
        if (d < PE_IN) {
            int c = threadIdx.x & 127;
            float acc = 0.f;
#pragma unroll
            for (int p = 0; p < NPE; p++)
                acc += (pe_w[d * NPE + p] + pe_b[p]) * edge_w[p * EDGE_C + c];
            g_PW[d * EDGE_C + c] = acc;
        }
    }
}

// ---------------------------------------------------------------------------
// Kernel 2: KNN select. One CTA (256 thr) handles 4 rows.
// Neighbor coords register-cached across rows (no SMEM coord tile).
// Histogram on top-11 bits of f32(D_adjust) -> boundary bin -> compact ->
// exact rank by 64-bit key count.
// ---------------------------------------------------------------------------
__global__ __launch_bounds__(256)
void knn_kernel(const float* __restrict__ bonds,
                const int*   __restrict__ resi,
                const int*   __restrict__ lig,
                float* __restrict__ outIdx,
                float* __restrict__ outD) {
    const int tid  = threadIdx.x;
    const int lane = tid & 31;
    const int wid  = tid >> 5;
    const int row0 = blockIdx.x * ROWS_PER_CTA;
    const int b    = row0 / NN;

    __shared__ int    sHist[NBIN];                  // 8 KB
    __shared__ unsigned long long sCand[CAND_CAP];  // 8 KB
    __shared__ float  sRed[8];
    __shared__ int    sWs[8];
    __shared__ int    sBinB, sNum;

    // register-cache this thread's 8 neighbor coords (same for all rows)
    float4 xj[8];
#pragma unroll
    for (int s = 0; s < 8; s++) xj[s] = g_X4[b * NN + tid + s * 256];

    for (int r = 0; r < ROWS_PER_CTA; r++) {
        const int row = row0 + r;
        const float4 xi = g_X4[row];

        // ---- distances: 8 neighbors per thread (pure register math) ----
        // masked-out pair  <=>  D == 0 exactly (live pairs have D >= 1e-3)
        float dloc[8];
        float vmax = 0.f;
#pragma unroll
        for (int s = 0; s < 8; s++) {
            float dx = xi.x - xj[s].x;
            float dy = xi.y - xj[s].y;
            float dz = xi.z - xj[s].z;
            float m2 = xi.w * xj[s].w;
            float D  = m2 * sqrtf(dx * dx + dy * dy + dz * dz + 1e-6f);
            dloc[s] = D;
            vmax = fmaxf(vmax, D);
        }
#pragma unroll
        for (int o = 16; o; o >>= 1) vmax = fmaxf(vmax, __shfl_xor_sync(0xffffffffu, vmax, o));
        if (lane == 0) sRed[wid] = vmax;
        // zero histogram while the max reduction settles
        *(int4*)(sHist + tid * 8)     = make_int4(0, 0, 0, 0);
        *(int4*)(sHist + tid * 8 + 4) = make_int4(0, 0, 0, 0);
        if (tid == 0) sNum = 0;
        __syncthreads();
        float Dmax = sRed[0];
#pragma unroll
        for (int w = 1; w < 8; w++) Dmax = fmaxf(Dmax, sRed[w]);

        // ---- keys (asc order == JAX top_k order incl. ties) ----
        unsigned long long keys[8];
#pragma unroll
        for (int s = 0; s < 8; s++) {
            int j = tid + s * 256;
            float Dadj = (dloc[s] == 0.f) ? Dmax : dloc[s];
            keys[s] = ((unsigned long long)__float_as_uint(Dadj) << 32) | (unsigned int)j;
        }

        // ---- histogram on top-11 bits (warp-aggregated atomics) ----
#pragma unroll
        for (int s = 0; s < 8; s++) {
            unsigned bin = (unsigned)(keys[s] >> 53);
            unsigned mm = __match_any_sync(0xffffffffu, bin);
            if (lane == (__ffs(mm) - 1))
                atomicAdd(&sHist[bin], __popc(mm));
        }
        __syncthreads();

        // ---- scan: 8 bins/thread serial + block scan of partials ----
        int psum = 0;
        int base = tid * 8;
#pragma unroll
        for (int t = 0; t < 8; t++) psum += sHist[base + t];
        int sc = psum;
#pragma unroll
        for (int o = 1; o < 32; o <<= 1) {
            int n = __shfl_up_sync(0xffffffffu, sc, o);
            if (lane >= o) sc += n;
        }
        if (lane == 31) sWs[wid] = sc;
        __syncthreads();
        if (wid == 0) {
            int wv = (lane < 8) ? sWs[lane] : 0;
#pragma unroll
            for (int o = 1; o < 8; o <<= 1) {
                int n = __shfl_up_sync(0xffffffffu, wv, o);
                if (lane >= o) wv += n;
            }
            if (lane < 8) sWs[lane] = wv;
        }
        __syncthreads();
        int excl = sc - psum + (wid ? sWs[wid - 1] : 0);
        int running = excl;
#pragma unroll
        for (int t = 0; t < 8; t++) {
            int c = sHist[base + t];
            if (running < KNN && running + c >= KNN) sBinB = base + t;
            running += c;
        }
        __syncthreads();
        const unsigned binB = (unsigned)sBinB;

        // ---- compact candidates: all keys in bins <= binB ----
#pragma unroll
        for (int s = 0; s < 8; s++) {
            if ((unsigned)(keys[s] >> 53) <= binB) {
                int p = atomicAdd(&sNum, 1);
                if (p < CAND_CAP) sCand[p] = keys[s];
            }
        }
        __syncthreads();
        int num = sNum < CAND_CAP ? sNum : CAND_CAP;

        // ---- exact rank by counting (LDS broadcast inner loop), emit ----
        for (int ci = tid; ci < num; ci += 256) {
            unsigned long long kk = sCand[ci];
            int rank = 0;
            for (int m = 0; m < num; m++) rank += (sCand[m] < kk);
            if (rank < KNN) {
                int   j = (int)(kk & 0xffffffffu);
                float D = __uint_as_float((unsigned int)(kk >> 32));
                int off = resi[row] - resi[b * NN + j];
                int dc = off + MAXREL;
                dc = dc < 0 ? 0 : (dc > 2 * MAXREL ? 2 * MAXREL : dc);
                float tb = bonds[(size_t)row * NN + j];
                tb = (lig[row] | lig[b * NN + j]) ? tb : 0.f;
                outIdx[(size_t)row * KNN + rank] = (float)j;
                outD  [(size_t)row * KNN + rank] = D;
                g_E4  [(size_t)row * KNN + rank] = make_float4(D, (float)dc, tb, 0.f);
            }
        }
        __syncthreads();   // protect sHist/sCand/sNum reuse across rows
    }
}

// ---------------------------------------------------------------------------
// Kernel 3: per-edge embed + layernorm. One warp per edge (x8 edges/warp).
// W2 in SMEM (broadcast reads), fused mean/var with 4-way interleaved
// shfl butterfly (independent chains pipeline the SHFL latency).
// ---------------------------------------------------------------------------
__global__ __launch_bounds__(256)
void edge_kernel(const float* __restrict__ edge_w,
                 const float* __restrict__ ln_g,
                 const float* __restrict__ ln_b,
                 float* __restrict__ outE) {
    const int tid  = threadIdx.x;
    const int lane = tid & 31;
    const int wid  = tid >> 5;

    __shared__ float sW2[NRBF * EDGE_C];   // 8 KB, broadcast in MAC loop

    for (int idx = tid * 4; idx < NRBF * EDGE_C; idx += 256 * 4)
        *(float4*)(sW2 + idx) = *(const float4*)(edge_w + NPE * EDGE_C + idx);

    const float4 w3 = *(const float4*)(edge_w + (NPE + NRBF) * EDGE_C + 4 * lane);
    const float4 lg = *(const float4*)(ln_g + 4 * lane);
    const float4 lb = *(const float4*)(ln_b + 4 * lane);
    const float mu_r = 2.f + (20.f / 15.f) * (float)(lane & 15);
    __syncthreads();

    const size_t e0 = (size_t)blockIdx.x * (8 * EDGES_PER_WARP) + (size_t)wid * EDGES_PER_WARP;

#pragma unroll
    for (int p = 0; p < EDGES_PER_WARP / 2; p++) {
        const size_t edge = e0 + 2 * p;
        float4 scA = g_E4[edge];
        float4 scB = g_E4[edge + 1];
        float4 pwA = *(const float4*)(g_PW + (int)scA.y * EDGE_C + 4 * lane);
        float4 pwB = *(const float4*)(g_PW + (int)scB.y * EDGE_C + 4 * lane);

        float ttA = (scA.x - mu_r) * (1.f / 1.25f);
        float ttB = (scB.x - mu_r) * (1.f / 1.25f);
        float rbfA = expf(-ttA * ttA);
        float rbfB = expf(-ttB * ttB);

        unsigned long long accA0 = pk2(fmaf(scA.z, w3.x, pwA.x), fmaf(scA.z, w3.y, pwA.y));
        unsigned long long accA1 = pk2(fmaf(scA.z, w3.z, pwA.z), fmaf(scA.z, w3.w, pwA.w));
        unsigned long long accB0 = pk2(fmaf(scB.z, w3.x, pwB.x), fmaf(scB.z, w3.y, pwB.y));
        unsigned long long accB1 = pk2(fmaf(scB.z, w3.z, pwB.z), fmaf(scB.z, w3.w, pwB.w));
#pragma unroll
        for (int r = 0; r < NRBF; r++) {
            float ra = __shfl_sync(0xffffffffu, rbfA, r);
            float rb = __shfl_sync(0xffffffffu, rbfB, r);
            const float4 wv = *(const float4*)(sW2 + r * EDGE_C + 4 * lane);
            unsigned long long w2lo = pk2(wv.x, wv.y);
            unsigned long long w2hi = pk2(wv.z, wv.w);
            accA0 = fma2(pk2(ra, ra), w2lo, accA0);
            accA1 = fma2(pk2(ra, ra), w2hi, accA1);
            accB0 = fma2(pk2(rb, rb), w2lo, accB0);
            accB1 = fma2(pk2(rb, rb), w2hi, accB1);
        }

        float a0, a1, a2, a3, b0, b1, b2, b3;
        unpk2(accA0, a0, a1); unpk2(accA1, a2, a3);
        unpk2(accB0, b0, b1); unpk2(accB1, b2, b3);

        // fused mean/var: 4 independent chains, one interleaved butterfly
        float sA  = (a0 + a1) + (a2 + a3);
        float sB  = (b0 + b1) + (b2 + b3);
        float qA  = (a0 * a0 + a1 * a1) + (a2 * a2 + a3 * a3);
        float qB  = (b0 * b0 + b1 * b1) + (b2 * b2 + b3 * b3);
#pragma unroll
        for (int o = 16; o; o >>= 1) {
            sA += __shfl_xor_sync(0xffffffffu, sA, o);
            sB += __shfl_xor_sync(0xffffffffu, sB, o);
            qA += __shfl_xor_sync(0xffffffffu, qA, o);
            qB += __shfl_xor_sync(0xffffffffu, qB, o);
        }
        float meanA = sA * (1.f / 128.f);
        float meanB = sB * (1.f / 128.f);
        float varA = fmaf(-meanA, meanA, qA * (1.f / 128.f));
        float varB = fmaf(-meanB, meanB, qB * (1.f / 128.f));
        float rstdA = rsqrtf(varA + 1e-5f);
        float rstdB = rsqrtf(varB + 1e-5f);

        float4 oA, oB;
        oA.x = (a0 - meanA) * rstdA * lg.x + lb.x;
        oA.y = (a1 - meanA) * rstdA * lg.y + lb.y;
        oA.z = (a2 - meanA) * rstdA * lg.z + lb.z;
        oA.w = (a3 - meanA) * rstdA * lg.w + lb.w;
        oB.x = (b0 - meanB) * rstdB * lg.x + lb.x;
        oB.y = (b1 - meanB) * rstdB * lg.y + lb.y;
        oB.z = (b2 - meanB) * rstdB * lg.z + lb.z;
        oB.w = (b3 - meanB) * rstdB * lg.w + lb.w;
        *(float4*)(outE + (edge)     * EDGE_C + 4 * lane) = oA;
        *(float4*)(outE + (edge + 1) * EDGE_C + 4 * lane) = oB;
    }
}

// ---------------------------------------------------------------------------
extern "C" void kernel_launch(void* const* d_in, const int* in_sizes, int n_in,
                              void* d_out, int out_size) {
    const float* coords = (const float*)d_in[0];
    const float* mask   = (const float*)d_in[1];
    const float* bonds  = (const float*)d_in[2];
    const float* pe_w   = (const float*)d_in[3];
    const float* pe_b   = (const float*)d_in[4];
    const float* edge_w = (const float*)d_in[5];
    const float* ln_g   = (const float*)d_in[6];
    const float* ln_b   = (const float*)d_in[7];
    const int*   t2c    = (const int*)d_in[8];
    const int*   resi   = (const int*)d_in[9];
    // d_in[10] = asym_id (unused: chain labels forced to zero in reference)
    const int*   lig    = (const int*)d_in[11];

    float* out    = (float*)d_out;
    float* outE   = out;                                        // B*N*K*128
    float* outIdx = out + (size_t)BB * NN * KNN * EDGE_C;       // B*N*K
    float* outD   = outIdx + (size_t)BB * NN * KNN;             // B*N*K

    setup_kernel<<<32 + (PE_IN + 1) / 2, 256>>>(coords, mask, t2c, pe_w, pe_b, edge_w);
    knn_kernel<<<BB * NN / ROWS_PER_CTA, 256>>>(bonds, resi, lig, outIdx, outD);
    edge_kernel<<<BB * NN * KNN / (8 * EDGES_PER_WARP), 256>>>(edge_w, ln_g, ln_b, outE);
}

// round 12
// speedup vs baseline: 1.5571x; 1.5571x over previous
#include <cuda_runtime.h>
#include <math.h>

#define BB 4
#define NN 2048
#define KNN 48
#define NRBF 16
#define NPE 16
#define EDGE_C 128
#define PE_IN 66
#define MAXREL 32
#define ROWS_PER_CTA 4
#define NBIN 2048
#define CAND_CAP 768
#define EDGES_PER_WARP 8

// scratch (no cudaMalloc allowed)
__device__ float4 g_X4[BB * NN];              // xyz = masked coords, w = mask
__device__ float  g_PW[PE_IN * EDGE_C];       // (pe_w[d]+pe_b) @ edge_w[0:16]
__device__ float4 g_E4[BB * NN * KNN];        // per-edge (D, dc, tb, -)

// f32x2 packed helpers
__device__ __forceinline__ unsigned long long pk2(float a, float b) {
    unsigned long long r;
    asm("mov.b64 %0, {%1, %2};" : "=l"(r) : "f"(a), "f"(b));
    return r;
}
__device__ __forceinline__ void unpk2(unsigned long long v, float& a, float& b) {
    asm("mov.b64 {%0, %1}, %2;" : "=f"(a), "=f"(b) : "l"(v));
}
__device__ __forceinline__ unsigned long long fma2(unsigned long long a,
                                                   unsigned long long b,
                                                   unsigned long long c) {
    unsigned long long d;
    asm("fma.rn.f32x2 %0, %1, %2, %3;" : "=l"(d) : "l"(a), "l"(b), "l"(c));
    return d;
}

// ---------------------------------------------------------------------------
// Kernel 1 (fused setup): blocks 0..31 gather coords; blocks 32..64 build PW.
// ---------------------------------------------------------------------------
__global__ void setup_kernel(const float* __restrict__ coords,
                             const float* __restrict__ mask,
                             const int*   __restrict__ t2c,
                             const float* __restrict__ pe_w,
                             const float* __restrict__ pe_b,
                             const float* __restrict__ edge_w) {
    if (blockIdx.x < 32) {
        int t = blockIdx.x * 256 + threadIdx.x;   // b*N + n
        int b = t / NN;
        int a = t2c[t];
        float m = mask[t];
        const float* src = coords + ((size_t)b * NN + a) * 3;
        g_X4[t] = make_float4(src[0] * m, src[1] * m, src[2] * m, m);
    } else {
        int d = (blockIdx.x - 32) * 2 + (threadIdx.x >> 7);   // 0..65
        if (d < PE_IN) {
            int c = threadIdx.x & 127;
            float acc = 0.f;
#pragma unroll
            for (int p = 0; p < NPE; p++)
                acc += (pe_w[d * NPE + p] + pe_b[p]) * edge_w[p * EDGE_C + c];
            g_PW[d * EDGE_C + c] = acc;
        }
    }
}

// ---------------------------------------------------------------------------
// Kernel 2: KNN select (exact R7 version). One CTA (256 thr) handles 4 rows,
// X tile in SMEM. Histogram on top-11 bits of f32(D_adjust) -> boundary bin
// -> compact candidates -> exact rank by 64-bit key count.
// ---------------------------------------------------------------------------
__global__ __launch_bounds__(256)
void knn_kernel(const float* __restrict__ bonds,
                const int*   __restrict__ resi,
                const int*   __restrict__ lig,
                float* __restrict__ outIdx,
                float* __restrict__ outD) {
    const int tid  = threadIdx.x;
    const int lane = tid & 31;
    const int wid  = tid >> 5;
    const int row0 = blockIdx.x * ROWS_PER_CTA;
    const int b    = row0 / NN;

    __shared__ float4 sX[NN];                       // 32 KB
    __shared__ int    sHist[NBIN];                  // 8 KB
    __shared__ unsigned long long sCand[CAND_CAP];  // 6 KB
    __shared__ float  sRed[8];
    __shared__ int    sWs[8];
    __shared__ int    sBinB, sNum;

    for (int idx = tid; idx < NN; idx += 256) sX[idx] = g_X4[b * NN + idx];
    __syncthreads();

    for (int r = 0; r < ROWS_PER_CTA; r++) {
        const int row = row0 + r;
        const int i   = row - b * NN;
        const float4 xi = sX[i];

        // ---- distances: 8 neighbors per thread ----
        float dloc[8], m2loc[8];
        float vmax = 0.f;
#pragma unroll
        for (int s = 0; s < 8; s++) {
            int j = tid + s * 256;
            float4 xj = sX[j];
            float dx = xi.x - xj.x;
            float dy = xi.y - xj.y;
            float dz = xi.z - xj.z;
            float m2 = xi.w * xj.w;
            float D  = m2 * sqrtf(dx * dx + dy * dy + dz * dz + 1e-6f);
            dloc[s] = D; m2loc[s] = m2;
            vmax = fmaxf(vmax, D);
        }
#pragma unroll
        for (int o = 16; o; o >>= 1) vmax = fmaxf(vmax, __shfl_xor_sync(0xffffffffu, vmax, o));
        if (lane == 0) sRed[wid] = vmax;
        // zero histogram while the max reduction settles
        *(int4*)(sHist + tid * 8)     = make_int4(0, 0, 0, 0);
        *(int4*)(sHist + tid * 8 + 4) = make_int4(0, 0, 0, 0);
        if (tid == 0) sNum = 0;
        __syncthreads();
        float Dmax = sRed[0];
#pragma unroll
        for (int w = 1; w < 8; w++) Dmax = fmaxf(Dmax, sRed[w]);

        // ---- keys (asc order == JAX top_k order incl. ties) ----
        unsigned long long keys[8];
#pragma unroll
        for (int s = 0; s < 8; s++) {
            int j = tid + s * 256;
            float Dadj = dloc[s] + (1.f - m2loc[s]) * Dmax;
            keys[s] = ((unsigned long long)__float_as_uint(Dadj) << 32) | (unsigned int)j;
        }

        // ---- histogram on top-11 bits (warp-aggregated atomics) ----
#pragma unroll
        for (int s = 0; s < 8; s++) {
            unsigned bin = (unsigned)(keys[s] >> 53);
            unsigned mm = __match_any_sync(0xffffffffu, bin);
            if (lane == (__ffs(mm) - 1))
                atomicAdd(&sHist[bin], __popc(mm));
        }
        __syncthreads();

        // ---- scan: 8 bins/thread serial + block scan of partials ----
        int psum = 0;
        int base = tid * 8;
#pragma unroll
        for (int t = 0; t < 8; t++) psum += sHist[base + t];
        int sc = psum;
#pragma unroll
        for (int o = 1; o < 32; o <<= 1) {
            int n = __shfl_up_sync(0xffffffffu, sc, o);
            if (lane >= o) sc += n;
        }
        if (lane == 31) sWs[wid] = sc;
        __syncthreads();
        if (wid == 0) {
            int wv = (lane < 8) ? sWs[lane] : 0;
#pragma unroll
            for (int o = 1; o < 8; o <<= 1) {
                int n = __shfl_up_sync(0xffffffffu, wv, o);
                if (lane >= o) wv += n;
            }
            if (lane < 8) sWs[lane] = wv;
        }
        __syncthreads();
        int excl = sc - psum + (wid ? sWs[wid - 1] : 0);
        int running = excl;
#pragma unroll
        for (int t = 0; t < 8; t++) {
            int c = sHist[base + t];
            if (running < KNN && running + c >= KNN) sBinB = base + t;
            running += c;
        }
        __syncthreads();
        const unsigned binB = (unsigned)sBinB;

        // ---- compact candidates: all keys in bins <= binB ----
#pragma unroll
        for (int s = 0; s < 8; s++) {
            if ((unsigned)(keys[s] >> 53) <= binB) {
                int p = atomicAdd(&sNum, 1);
                if (p < CAND_CAP) sCand[p] = keys[s];
            }
        }
        __syncthreads();
        int num = sNum < CAND_CAP ? sNum : CAND_CAP;

        // ---- exact rank by counting (LDS broadcast inner loop), emit ----
        for (int ci = tid; ci < num; ci += 256) {
            unsigned long long kk = sCand[ci];
            int rank = 0;
            for (int m = 0; m < num; m++) rank += (sCand[m] < kk);
            if (rank < KNN) {
                int   j = (int)(kk & 0xffffffffu);
                float D = __uint_as_float((unsigned int)(kk >> 32));
                int off = resi[row] - resi[b * NN + j];
                int dc = off + MAXREL;
                dc = dc < 0 ? 0 : (dc > 2 * MAXREL ? 2 * MAXREL : dc);
                float tb = bonds[(size_t)row * NN + j];
                tb = (lig[row] | lig[b * NN + j]) ? tb : 0.f;
                outIdx[(size_t)row * KNN + rank] = (float)j;
                outD  [(size_t)row * KNN + rank] = D;
                g_E4  [(size_t)row * KNN + rank] = make_float4(D, (float)dc, tb, 0.f);
            }
        }
        __syncthreads();   // protect sHist/sCand/sNum reuse across rows
    }
}

// ---------------------------------------------------------------------------
// Kernel 3: per-edge embed + layernorm. One warp per edge (x8 edges/warp).
// W2 in SMEM, read as ulonglong2 so LDS.128 lands directly in f32x2 operand
// pairs (no repack movs). Fused mean/var, 4-way interleaved shfl butterfly.
// ---------------------------------------------------------------------------
__global__ __launch_bounds__(256)
void edge_kernel(const float* __restrict__ edge_w,
                 const float* __restrict__ ln_g,
                 const float* __restrict__ ln_b,
                 float* __restrict__ outE) {
    const int tid  = threadIdx.x;
    const int lane = tid & 31;
    const int wid  = tid >> 5;

    __shared__ __align__(16) float sW2[NRBF * EDGE_C];   // 8 KB

    for (int idx = tid * 4; idx < NRBF * EDGE_C; idx += 256 * 4)
        *(float4*)(sW2 + idx) = *(const float4*)(edge_w + NPE * EDGE_C + idx);

    const float4 w3 = *(const float4*)(edge_w + (NPE + NRBF) * EDGE_C + 4 * lane);
    const float4 lg = *(const float4*)(ln_g + 4 * lane);
    const float4 lb = *(const float4*)(ln_b + 4 * lane);
    const float mu_r = 2.f + (20.f / 15.f) * (float)(lane & 15);
    __syncthreads();

    const size_t e0 = (size_t)blockIdx.x * (8 * EDGES_PER_WARP) + (size_t)wid * EDGES_PER_WARP;

#pragma unroll
    for (int p = 0; p < EDGES_PER_WARP / 2; p++) {
        const size_t edge = e0 + 2 * p;
        float4 scA = g_E4[edge];
        float4 scB = g_E4[edge + 1];
        float4 pwA = *(const float4*)(g_PW + (int)scA.y * EDGE_C + 4 * lane);
        float4 pwB = *(const float4*)(g_PW + (int)scB.y * EDGE_C + 4 * lane);

        float ttA = (scA.x - mu_r) * (1.f / 1.25f);
        float ttB = (scB.x - mu_r) * (1.f / 1.25f);
        float rbfA = expf(-ttA * ttA);
        float rbfB = expf(-ttB * ttB);

        unsigned long long accA0 = pk2(fmaf(scA.z, w3.x, pwA.x), fmaf(scA.z, w3.y, pwA.y));
        unsigned long long accA1 = pk2(fmaf(scA.z, w3.z, pwA.z), fmaf(scA.z, w3.w, pwA.w));
        unsigned long long accB0 = pk2(fmaf(scB.z, w3.x, pwB.x), fmaf(scB.z, w3.y, pwB.y));
        unsigned long long accB1 = pk2(fmaf(scB.z, w3.z, pwB.z), fmaf(scB.z, w3.w, pwB.w));
#pragma unroll
        for (int r = 0; r < NRBF; r++) {
            float ra = __shfl_sync(0xffffffffu, rbfA, r);
            float rb = __shfl_sync(0xffffffffu, rbfB, r);
            const ulonglong2 wv = *(const ulonglong2*)(sW2 + r * EDGE_C + 4 * lane);
            unsigned long long ra2 = pk2(ra, ra);
            unsigned long long rb2 = pk2(rb, rb);
            accA0 = fma2(ra2, wv.x, accA0);
            accA1 = fma2(ra2, wv.y, accA1);
            accB0 = fma2(rb2, wv.x, accB0);
            accB1 = fma2(rb2, wv.y, accB1);
        }

        float a0, a1, a2, a3, b0, b1, b2, b3;
        unpk2(accA0, a0, a1); unpk2(accA1, a2, a3);
        unpk2(accB0, b0, b1); unpk2(accB1, b2, b3);

        // fused mean/var: 4 independent chains, one interleaved butterfly
        float sA  = (a0 + a1) + (a2 + a3);
        float sB  = (b0 + b1) + (b2 + b3);
        float qA  = (a0 * a0 + a1 * a1) + (a2 * a2 + a3 * a3);
        float qB  = (b0 * b0 + b1 * b1) + (b2 * b2 + b3 * b3);
#pragma unroll
        for (int o = 16; o; o >>= 1) {
            sA += __shfl_xor_sync(0xffffffffu, sA, o);
            sB += __shfl_xor_sync(0xffffffffu, sB, o);
            qA += __shfl_xor_sync(0xffffffffu, qA, o);
            qB += __shfl_xor_sync(0xffffffffu, qB, o);
        }
        float meanA = sA * (1.f / 128.f);
        float meanB = sB * (1.f / 128.f);
        float varA = fmaf(-meanA, meanA, qA * (1.f / 128.f));
        float varB = fmaf(-meanB, meanB, qB * (1.f / 128.f));
        float rstdA = rsqrtf(varA + 1e-5f);
        float rstdB = rsqrtf(varB + 1e-5f);

        float4 oA, oB;
        oA.x = (a0 - meanA) * rstdA * lg.x + lb.x;
        oA.y = (a1 - meanA) * rstdA * lg.y + lb.y;
        oA.z = (a2 - meanA) * rstdA * lg.z + lb.z;
        oA.w = (a3 - meanA) * rstdA * lg.w + lb.w;
        oB.x = (b0 - meanB) * rstdB * lg.x + lb.x;
        oB.y = (b1 - meanB) * rstdB * lg.y + lb.y;
        oB.z = (b2 - meanB) * rstdB * lg.z + lb.z;
        oB.w = (b3 - meanB) * rstdB * lg.w + lb.w;
        *(float4*)(outE + (edge)     * EDGE_C + 4 * lane) = oA;
        *(float4*)(outE + (edge + 1) * EDGE_C + 4 * lane) = oB;
    }
}

// ---------------------------------------------------------------------------
extern "C" void kernel_launch(void* const* d_in, const int* in_sizes, int n_in,
                              void* d_out, int out_size) {
    const float* coords = (const float*)d_in[0];
    const float* mask   = (const float*)d_in[1];
    const float* bonds  = (const float*)d_in[2];
    const float* pe_w   = (const float*)d_in[3];
    const float* pe_b   = (const float*)d_in[4];
    const float* edge_w = (const float*)d_in[5];
    const float* ln_g   = (const float*)d_in[6];
    const float* ln_b   = (const float*)d_in[7];
    const int*   t2c    = (const int*)d_in[8];
    const int*   resi   = (const int*)d_in[9];
    // d_in[10] = asym_id (unused: chain labels forced to zero in reference)
    const int*   lig    = (const int*)d_in[11];

    float* out    = (float*)d_out;
    float* outE   = out;                                        // B*N*K*128
    float* outIdx = out + (size_t)BB * NN * KNN * EDGE_C;       // B*N*K
    float* outD   = outIdx + (size_t)BB * NN * KNN;             // B*N*K

    setup_kernel<<<32 + (PE_IN + 1) / 2, 256>>>(coords, mask, t2c, pe_w, pe_b, edge_w);
    knn_kernel<<<BB * NN / ROWS_PER_CTA, 256>>>(bonds, resi, lig, outIdx, outD);
    edge_kernel<<<BB * NN * KNN / (8 * EDGES_PER_WARP), 256>>>(edge_w, ln_g, ln_b, outE);
}

// round 14
// speedup vs baseline: 1.7257x; 1.1083x over previous
#include <cuda_runtime.h>
#include <math.h>

#define BB 4
#define NN 2048
#define KNN 48
#define NRBF 16
#define NPE 16
#define EDGE_C 128
#define PE_IN 66
#define MAXREL 32
#define ROWS_PER_CTA 4
#define NBIN 2048
#define CAND_CAP 768
#define EDGES_PER_WARP 16

// scratch (no cudaMalloc allowed)
__device__ float4 g_X4[BB * NN];              // xyz = masked coords, w = mask
__device__ float  g_PW[PE_IN * EDGE_C];       // (pe_w[d]+pe_b) @ edge_w[0:16]
__device__ float4 g_E4[BB * NN * KNN];        // per-edge (D, dc, tb, -)

// f32x2 packed helpers
__device__ __forceinline__ unsigned long long pk2(float a, float b) {
    unsigned long long r;
    asm("mov.b64 %0, {%1, %2};" : "=l"(r) : "f"(a), "f"(b));
    return r;
}
__device__ __forceinline__ void unpk2(unsigned long long v, float& a, float& b) {
    asm("mov.b64 {%0, %1}, %2;" : "=f"(a), "=f"(b) : "l"(v));
}
__device__ __forceinline__ unsigned long long fma2(unsigned long long a,
                                                   unsigned long long b,
                                                   unsigned long long c) {
    unsigned long long d;
    asm("fma.rn.f32x2 %0, %1, %2, %3;" : "=l"(d) : "l"(a), "l"(b), "l"(c));
    return d;
}

// ---------------------------------------------------------------------------
// Kernel 1 (fused setup): blocks 0..31 gather coords; blocks 32..64 build PW.
// ---------------------------------------------------------------------------
__global__ void setup_kernel(const float* __restrict__ coords,
                             const float* __restrict__ mask,
                             const int*   __restrict__ t2c,
                             const float* __restrict__ pe_w,
                             const float* __restrict__ pe_b,
                             const float* __restrict__ edge_w) {
    if (blockIdx.x < 32) {
        int t = blockIdx.x * 256 + threadIdx.x;   // b*N + n
        int b = t / NN;
        int a = t2c[t];
        float m = mask[t];
        const float* src = coords + ((size_t)b * NN + a) * 3;
        g_X4[t] = make_float4(src[0] * m, src[1] * m, src[2] * m, m);
    } else {
        int d = (blockIdx.x - 32) * 2 + (threadIdx.x >> 7);   // 0..65
        if (d < PE_IN) {
            int c = threadIdx.x & 127;
            float acc = 0.f;
#pragma unroll
            for (int p = 0; p < NPE; p++)
                acc += (pe_w[d * NPE + p] + pe_b[p]) * edge_w[p * EDGE_C + c];
            g_PW[d * EDGE_C + c] = acc;
        }
    }
}

// ---------------------------------------------------------------------------
// Kernel 2: KNN select (R7-exact, known-good). One CTA / 4 rows, X in SMEM.
// ---------------------------------------------------------------------------
__global__ __launch_bounds__(256)
void knn_kernel(const float* __restrict__ bonds,
                const int*   __restrict__ resi,
                const int*   __restrict__ lig,
                float* __restrict__ outIdx,
                float* __restrict__ outD) {
    const int tid  = threadIdx.x;
    const int lane = tid & 31;
    const int wid  = tid >> 5;
    const int row0 = blockIdx.x * ROWS_PER_CTA;
    const int b    = row0 / NN;

    __shared__ float4 sX[NN];                       // 32 KB
    __shared__ int    sHist[NBIN];                  // 8 KB
    __shared__ unsigned long long sCand[CAND_CAP];  // 6 KB
    __shared__ float  sRed[8];
    __shared__ int    sWs[8];
    __shared__ int    sBinB, sNum;

    for (int idx = tid; idx < NN; idx += 256) sX[idx] = g_X4[b * NN + idx];
    __syncthreads();

    for (int r = 0; r < ROWS_PER_CTA; r++) {
        const int row = row0 + r;
        const int i   = row - b * NN;
        const float4 xi = sX[i];

        float dloc[8], m2loc[8];
        float vmax = 0.f;
#pragma unroll
        for (int s = 0; s < 8; s++) {
            int j = tid + s * 256;
            float4 xj = sX[j];
            float dx = xi.x - xj.x;
            float dy = xi.y - xj.y;
            float dz = xi.z - xj.z;
            float m2 = xi.w * xj.w;
            float D  = m2 * sqrtf(dx * dx + dy * dy + dz * dz + 1e-6f);
            dloc[s] = D; m2loc[s] = m2;
            vmax = fmaxf(vmax, D);
        }
#pragma unroll
        for (int o = 16; o; o >>= 1) vmax = fmaxf(vmax, __shfl_xor_sync(0xffffffffu, vmax, o));
        if (lane == 0) sRed[wid] = vmax;
        *(int4*)(sHist + tid * 8)     = make_int4(0, 0, 0, 0);
        *(int4*)(sHist + tid * 8 + 4) = make_int4(0, 0, 0, 0);
        if (tid == 0) sNum = 0;
        __syncthreads();
        float Dmax = sRed[0];
#pragma unroll
        for (int w = 1; w < 8; w++) Dmax = fmaxf(Dmax, sRed[w]);

        unsigned long long keys[8];
#pragma unroll
        for (int s = 0; s < 8; s++) {
            int j = tid + s * 256;
            float Dadj = dloc[s] + (1.f - m2loc[s]) * Dmax;
            keys[s] = ((unsigned long long)__float_as_uint(Dadj) << 32) | (unsigned int)j;
        }

#pragma unroll
        for (int s = 0; s < 8; s++) {
            unsigned bin = (unsigned)(keys[s] >> 53);
            unsigned mm = __match_any_sync(0xffffffffu, bin);
            if (lane == (__ffs(mm) - 1))
                atomicAdd(&sHist[bin], __popc(mm));
        }
        __syncthreads();

        int psum = 0;
        int base = tid * 8;
#pragma unroll
        for (int t = 0; t < 8; t++) psum += sHist[base + t];
        int sc = psum;
#pragma unroll
        for (int o = 1; o < 32; o <<= 1) {
            int n = __shfl_up_sync(0xffffffffu, sc, o);
            if (lane >= o) sc += n;
        }
        if (lane == 31) sWs[wid] = sc;
        __syncthreads();
        if (wid == 0) {
            int wv = (lane < 8) ? sWs[lane] : 0;
#pragma unroll
            for (int o = 1; o < 8; o <<= 1) {
                int n = __shfl_up_sync(0xffffffffu, wv, o);
                if (lane >= o) wv += n;
            }
            if (lane < 8) sWs[lane] = wv;
        }
        __syncthreads();
        int excl = sc - psum + (wid ? sWs[wid - 1] : 0);
        int running = excl;
#pragma unroll
        for (int t = 0; t < 8; t++) {
            int c = sHist[base + t];
            if (running < KNN && running + c >= KNN) sBinB = base + t;
            running += c;
        }
        __syncthreads();
        const unsigned binB = (unsigned)sBinB;

#pragma unroll
        for (int s = 0; s < 8; s++) {
            if ((unsigned)(keys[s] >> 53) <= binB) {
                int p = atomicAdd(&sNum, 1);
                if (p < CAND_CAP) sCand[p] = keys[s];
            }
        }
        __syncthreads();
        int num = sNum < CAND_CAP ? sNum : CAND_CAP;

        for (int ci = tid; ci < num; ci += 256) {
            unsigned long long kk = sCand[ci];
            int rank = 0;
            for (int m = 0; m < num; m++) rank += (sCand[m] < kk);
            if (rank < KNN) {
                int   j = (int)(kk & 0xffffffffu);
                float D = __uint_as_float((unsigned int)(kk >> 32));
                int off = resi[row] - resi[b * NN + j];
                int dc = off + MAXREL;
                dc = dc < 0 ? 0 : (dc > 2 * MAXREL ? 2 * MAXREL : dc);
                float tb = bonds[(size_t)row * NN + j];
                tb = (lig[row] | lig[b * NN + j]) ? tb : 0.f;
                outIdx[(size_t)row * KNN + rank] = (float)j;
                outD  [(size_t)row * KNN + rank] = D;
                g_E4  [(size_t)row * KNN + rank] = make_float4(D, (float)dc, tb, 0.f);
            }
        }
        __syncthreads();
    }
}

// ---------------------------------------------------------------------------
// Kernel 3: per-edge embed + layernorm. 4 edges per warp-iteration:
// each SMEM W2 LDS.128 feeds 8 fma2 (4 edges x 2 packed channels).
// Lanes 0-15 hold rbf for edges {0,2}; lanes 16-31 for edges {1,3}.
// Next-group g_E4 prefetch; fused mean/var; 8-chain interleaved butterfly.
// ---------------------------------------------------------------------------
__global__ __launch_bounds__(256)
void edge_kernel(const float* __restrict__ edge_w,
                 const float* __restrict__ ln_g,
                 const float* __restrict__ ln_b,
                 float* __restrict__ outE) {
    const int tid  = threadIdx.x;
    const int lane = tid & 31;
    const int wid  = tid >> 5;

    __shared__ __align__(16) float sW2[NRBF * EDGE_C];   // 8 KB

    for (int idx = tid * 4; idx < NRBF * EDGE_C; idx += 256 * 4)
        *(float4*)(sW2 + idx) = *(const float4*)(edge_w + NPE * EDGE_C + idx);

    const float4 w3 = *(const float4*)(edge_w + (NPE + NRBF) * EDGE_C + 4 * lane);
    const float4 lg = *(const float4*)(ln_g + 4 * lane);
    const float4 lb = *(const float4*)(ln_b + 4 * lane);
    const float mu_r = 2.f + (20.f / 15.f) * (float)(lane & 15);
    const bool  lo16 = (lane < 16);
    __syncthreads();

    const size_t e0 = (size_t)blockIdx.x * (8 * EDGES_PER_WARP) + (size_t)wid * EDGES_PER_WARP;

    float4 sc0 = g_E4[e0], sc1 = g_E4[e0 + 1], sc2 = g_E4[e0 + 2], sc3 = g_E4[e0 + 3];

#pragma unroll
    for (int g = 0; g < EDGES_PER_WARP / 4; g++) {
        const size_t edge = e0 + g * 4;
        // prefetch next group's scalars
        float4 n0, n1, n2, n3;
        if (g < EDGES_PER_WARP / 4 - 1) {
            n0 = g_E4[edge + 4]; n1 = g_E4[edge + 5];
            n2 = g_E4[edge + 6]; n3 = g_E4[edge + 7];
        }

        const float4 pw0 = *(const float4*)(g_PW + (int)sc0.y * EDGE_C + 4 * lane);
        const float4 pw1 = *(const float4*)(g_PW + (int)sc1.y * EDGE_C + 4 * lane);
        const float4 pw2 = *(const float4*)(g_PW + (int)sc2.y * EDGE_C + 4 * lane);
        const float4 pw3 = *(const float4*)(g_PW + (int)sc3.y * EDGE_C + 4 * lane);

        // rbf: lanes 0-15 -> edges 0,2 ; lanes 16-31 -> edges 1,3
        float D01 = lo16 ? sc0.x : sc1.x;
        float D23 = lo16 ? sc2.x : sc3.x;
        float t1 = (D01 - mu_r) * 0.8f;
        float t2 = (D23 - mu_r) * 0.8f;
        float rbfP1 = expf(-t1 * t1);
        float rbfP2 = expf(-t2 * t2);

        unsigned long long a00 = pk2(fmaf(sc0.z, w3.x, pw0.x), fmaf(sc0.z, w3.y, pw0.y));
        unsigned long long a01 = pk2(fmaf(sc0.z, w3.z, pw0.z), fmaf(sc0.z, w3.w, pw0.w));
        unsigned long long a10 = pk2(fmaf(sc1.z, w3.x, pw1.x), fmaf(sc1.z, w3.y, pw1.y));
        unsigned long long a11 = pk2(fmaf(sc1.z, w3.z, pw1.z), fmaf(sc1.z, w3.w, pw1.w));
        unsigned long long a20 = pk2(fmaf(sc2.z, w3.x, pw2.x), fmaf(sc2.z, w3.y, pw2.y));
        unsigned long long a21 = pk2(fmaf(sc2.z, w3.z, pw2.z), fmaf(sc2.z, w3.w, pw2.w));
        unsigned long long a30 = pk2(fmaf(sc3.z, w3.x, pw3.x), fmaf(sc3.z, w3.y, pw3.y));
        unsigned long long a31 = pk2(fmaf(sc3.z, w3.z, pw3.z), fmaf(sc3.z, w3.w, pw3.w));

#pragma unroll
        for (int r = 0; r < NRBF; r++) {
            float b0 = __shfl_sync(0xffffffffu, rbfP1, r);
            float b1 = __shfl_sync(0xffffffffu, rbfP1, r + 16);
            float b2 = __shfl_sync(0xffffffffu, rbfP2, r);
            float b3 = __shfl_sync(0xffffffffu, rbfP2, r + 16);
            const ulonglong2 wv = *(const ulonglong2*)(sW2 + r * EDGE_C + 4 * lane);
            unsigned long long p0 = pk2(b0, b0);
            unsigned long long p1 = pk2(b1, b1);
            unsigned long long p2 = pk2(b2, b2);
            unsigned long long p3 = pk2(b3, b3);
            a00 = fma2(p0, wv.x, a00); a01 = fma2(p0, wv.y, a01);
            a10 = fma2(p1, wv.x, a10); a11 = fma2(p1, wv.y, a11);
            a20 = fma2(p2, wv.x, a20); a21 = fma2(p2, wv.y, a21);
            a30 = fma2(p3, wv.x, a30); a31 = fma2(p3, wv.y, a31);
        }

        float v0[4], v1[4], v2[4], v3[4];
        unpk2(a00, v0[0], v0[1]); unpk2(a01, v0[2], v0[3]);
        unpk2(a10, v1[0], v1[1]); unpk2(a11, v1[2], v1[3]);
        unpk2(a20, v2[0], v2[1]); unpk2(a21, v2[2], v2[3]);
        unpk2(a30, v3[0], v3[1]); unpk2(a31, v3[2], v3[3]);

        // fused mean/var: 8 independent chains, one interleaved butterfly
        float s0 = (v0[0] + v0[1]) + (v0[2] + v0[3]);
        float s1 = (v1[0] + v1[1]) + (v1[2] + v1[3]);
        float s2 = (v2[0] + v2[1]) + (v2[2] + v2[3]);
        float s3 = (v3[0] + v3[1]) + (v3[2] + v3[3]);
        float q0 = (v0[0] * v0[0] + v0[1] * v0[1]) + (v0[2] * v0[2] + v0[3] * v0[3]);
        float q1 = (v1[0] * v1[0] + v1[1] * v1[1]) + (v1[2] * v1[2] + v1[3] * v1[3]);
        float q2 = (v2[0] * v2[0] + v2[1] * v2[1]) + (v2[2] * v2[2] + v2[3] * v2[3]);
        float q3 = (v3[0] * v3[0] + v3[1] * v3[1]) + (v3[2] * v3[2] + v3[3] * v3[3]);
#pragma unroll
        for (int o = 16; o; o >>= 1) {
            s0 += __shfl_xor_sync(0xffffffffu, s0, o);
            s1 += __shfl_xor_sync(0xffffffffu, s1, o);
            s2 += __shfl_xor_sync(0xffffffffu, s2, o);
            s3 += __shfl_xor_sync(0xffffffffu, s3, o);
            q0 += __shfl_xor_sync(0xffffffffu, q0, o);
            q1 += __shfl_xor_sync(0xffffffffu, q1, o);
            q2 += __shfl_xor_sync(0xffffffffu, q2, o);
            q3 += __shfl_xor_sync(0xffffffffu, q3, o);
        }
        float m0 = s0 * (1.f / 128.f), m1 = s1 * (1.f / 128.f);
        float m2 = s2 * (1.f / 128.f), m3 = s3 * (1.f / 128.f);
        float r0 = rsqrtf(fmaf(-m0, m0, q0 * (1.f / 128.f)) + 1e-5f);
        float r1 = rsqrtf(fmaf(-m1, m1, q1 * (1.f / 128.f)) + 1e-5f);
        float r2 = rsqrtf(fmaf(-m2, m2, q2 * (1.f / 128.f)) + 1e-5f);
        float r3 = rsqrtf(fmaf(-m3, m3, q3 * (1.f / 128.f)) + 1e-5f);

        float4 o4;
        o4.x = (v0[0] - m0) * r0 * lg.x + lb.x;
        o4.y = (v0[1] - m0) * r0 * lg.y + lb.y;
        o4.z = (v0[2] - m0) * r0 * lg.z + lb.z;
        o4.w = (v0[3] - m0) * r0 * lg.w + lb.w;
        *(float4*)(outE + (edge)     * EDGE_C + 4 * lane) = o4;
        o4.x = (v1[0] - m1) * r1 * lg.x + lb.x;
        o4.y = (v1[1] - m1) * r1 * lg.y + lb.y;
        o4.z = (v1[2] - m1) * r1 * lg.z + lb.z;
        o4.w = (v1[3] - m1) * r1 * lg.w + lb.w;
        *(float4*)(outE + (edge + 1) * EDGE_C + 4 * lane) = o4;
        o4.x = (v2[0] - m2) * r2 * lg.x + lb.x;
        o4.y = (v2[1] - m2) * r2 * lg.y + lb.y;
        o4.z = (v2[2] - m2) * r2 * lg.z + lb.z;
        o4.w = (v2[3] - m2) * r2 * lg.w + lb.w;
        *(float4*)(outE + (edge + 2) * EDGE_C + 4 * lane) = o4;
        o4.x = (v3[0] - m3) * r3 * lg.x + lb.x;
        o4.y = (v3[1] - m3) * r3 * lg.y + lb.y;
        o4.z = (v3[2] - m3) * r3 * lg.z + lb.z;
        o4.w = (v3[3] - m3) * r3 * lg.w + lb.w;
        *(float4*)(outE + (edge + 3) * EDGE_C + 4 * lane) = o4;

        sc0 = n0; sc1 = n1; sc2 = n2; sc3 = n3;
    }
}

// ---------------------------------------------------------------------------
extern "C" void kernel_launch(void* const* d_in, const int* in_sizes, int n_in,
                              void* d_out, int out_size) {
    const float* coords = (const float*)d_in[0];
    const float* mask   = (const float*)d_in[1];
    const float* bonds  = (const float*)d_in[2];
    const float* pe_w   = (const float*)d_in[3];
    const float* pe_b   = (const float*)d_in[4];
    const float* edge_w = (const float*)d_in[5];
    const float* ln_g   = (const float*)d_in[6];
    const float* ln_b   = (const float*)d_in[7];
    const int*   t2c    = (const int*)d_in[8];
    const int*   resi   = (const int*)d_in[9];
    // d_in[10] = asym_id (unused: chain labels forced to zero in reference)
    const int*   lig    = (const int*)d_in[11];

    float* out    = (float*)d_out;
    float* outE   = out;                                        // B*N*K*128
    float* outIdx = out + (size_t)BB * NN * KNN * EDGE_C;       // B*N*K
    float* outD   = outIdx + (size_t)BB * NN * KNN;             // B*N*K

    setup_kernel<<<32 + (PE_IN + 1) / 2, 256>>>(coords, mask, t2c, pe_w, pe_b, edge_w);
    knn_kernel<<<BB * NN / ROWS_PER_CTA, 256>>>(bonds, resi, lig, outIdx, outD);
    edge_kernel<<<BB * NN * KNN / (8 * EDGES_PER_WARP), 256>>>(edge_w, ln_g, ln_b, outE);
}